// round 2
// baseline (speedup 1.0000x reference)
#include <cuda_runtime.h>

// SphereDownGeo: y[c,k] = sum_d M_vals[k,d] * x[c, M_cols[k,d]]
// M_cols[k,d] = clip(4k + off, 0, N-1), off in [-6,10) -> windowed gather.
// Block of KPB consecutive k's covers x window [4*k0-6, 4*k0+4*KPB+5],
// span = 4*KPB+16 elements per channel. Stage in SMEM, gather locally.

#define KPB   256
#define DEG   16
#define CCH   8
#define SEG   (4 * KPB + 16)   // 1040 floats per channel window

__global__ __launch_bounds__(KPB)
void sphere_down_kernel(const float*  __restrict__ x,
                        const int*    __restrict__ M_cols,
                        const float*  __restrict__ M_vals,
                        const int*    __restrict__ cell_ids,
                        float*        __restrict__ out,
                        int n_in, int k_out)
{
    __shared__ float xs[CCH][SEG];

    const int k0 = blockIdx.x * KPB;
    const int t  = threadIdx.x;
    const int k  = k0 + t;

    // Window origin. Clipped cols always land in [lo, lo+SEG) ∩ [0, n_in):
    // clip only moves a column toward the valid range.
    int lo = 4 * k0 - 6;
    if (lo < 0) lo = 0;

    // ---- Stage x window for all 8 channels (coalesced, flattened so the
    //      compiler batches independent LDGs for max MLP) ----
    for (int j = t; j < CCH * SEG; j += KPB) {
        int c = j / SEG;
        int i = j - c * SEG;
        int g = lo + i;
        xs[c][i] = (g < n_in) ? x[(size_t)c * n_in + g] : 0.0f;
    }

    // ---- Load this thread's 16 cols / 16 weights (vectorized; row k starts
    //      at a 64B boundary so int4/float4 are aligned and coalesced) ----
    int   cols[DEG];
    float vals[DEG];
    {
        const int4*   cp = (const int4*)(M_cols + (size_t)k * DEG);
        const float4* vp = (const float4*)(M_vals + (size_t)k * DEG);
        #pragma unroll
        for (int i = 0; i < 4; i++) {
            int4   c4 = cp[i];
            float4 v4 = vp[i];
            cols[4*i + 0] = c4.x - lo;  vals[4*i + 0] = v4.x;
            cols[4*i + 1] = c4.y - lo;  vals[4*i + 1] = v4.y;
            cols[4*i + 2] = c4.z - lo;  vals[4*i + 2] = v4.z;
            cols[4*i + 3] = c4.w - lo;  vals[4*i + 3] = v4.w;
        }
    }

    __syncthreads();

    // ---- Gather-reduce per channel, coalesced store ----
    #pragma unroll
    for (int c = 0; c < CCH; c++) {
        float acc = 0.0f;
        #pragma unroll
        for (int d = 0; d < DEG; d++)
            acc = fmaf(vals[d], xs[c][cols[d]], acc);
        out[(size_t)c * k_out + k] = acc;
    }

    // ---- cell_ids pass-through (second tuple element), as float in the
    //      concatenated float32 output buffer ----
    out[(size_t)CCH * k_out + k] = (float)cell_ids[k];
}

extern "C" void kernel_launch(void* const* d_in, const int* in_sizes, int n_in_args,
                              void* d_out, int out_size)
{
    const float* x        = (const float*)d_in[0];   // (1, 8, N_IN) f32
    const int*   M_cols   = (const int*)  d_in[1];   // (K_OUT, 16) i32
    const float* M_vals   = (const float*)d_in[2];   // (K_OUT, 16) f32
    const int*   cell_ids = (const int*)  d_in[3];   // (K_OUT,)    i32

    const int N_IN  = in_sizes[0] / CCH;      // 3,145,728
    const int K_OUT = in_sizes[3];            // 786,432

    float* out = (float*)d_out;

    const int grid = (K_OUT + KPB - 1) / KPB; // 3072, exact
    sphere_down_kernel<<<grid, KPB>>>(x, M_cols, M_vals, cell_ids, out,
                                      N_IN, K_OUT);
}